// round 3
// baseline (speedup 1.0000x reference)
#include <cuda_runtime.h>
#include <cuda_bf16.h>
#include <math.h>

#define CC 2048
#define GG 4
#define LL 512
#define NT 16384
#define EPSV 1e-4f
#define KS 16
#define KCH (NT/KS)
#define NS_ITERS 5
#define SQ_ITERS 16

// ---------------- device scratch (static, no allocations) ----------------
__device__ float g_part[KS][GG][LL][LL];   // cov split-K partials
__device__ float g_A[GG][LL][LL];          // covariance + eps I (full symmetric)
__device__ float g_Y[2][GG][LL][LL];
__device__ float g_Z[2][GG][LL][LL];
__device__ float g_T[GG][LL][LL];
__device__ float g_M[2][GG][LL][LL];       // squaring ping-pong
__device__ float g_P[GG][LL][LL];          // final subspace
__device__ float g_mu[CC];
__device__ float g_pv[2][GG][LL];          // power-iteration vectors
__device__ float g_v[GG][LL];              // smallest eigenvector
__device__ float g_beta[CC];
__device__ float g_scal[16];               // [g]=RQ(lam_max est), [8+g]=lam_min
__device__ float g_fsq[SQ_ITERS + 1][GG];  // Frobenius^2 chain
__device__ float g_red[GG][16];            // per-tile partials

__device__ __forceinline__ float* bufptr(int id) {
    switch (id) {
        case 0: return &g_Y[0][0][0][0];
        case 1: return &g_Y[1][0][0][0];
        case 2: return &g_Z[0][0][0][0];
        case 3: return &g_Z[1][0][0][0];
        case 4: return &g_T[0][0][0];
        case 5: return &g_M[0][0][0][0];
        case 6: return &g_M[1][0][0][0];
        default: return &g_A[0][0][0];
    }
}

// ---------------- per-channel mean ----------------
__global__ __launch_bounds__(256) void k_mean(const float* __restrict__ x) {
    __shared__ float sm[256];
    int c = blockIdx.x;
    const float4* row = (const float4*)(x + (size_t)c * NT);
    float s = 0.f;
    for (int i = threadIdx.x; i < NT / 4; i += 256) {
        float4 v = row[i];
        s += (v.x + v.y) + (v.z + v.w);
    }
    int t = threadIdx.x;
    sm[t] = s; __syncthreads();
    for (int o = 128; o > 0; o >>= 1) { if (t < o) sm[t] += sm[t + o]; __syncthreads(); }
    if (t == 0) g_mu[c] = sm[0] * (1.f / NT);
}

// ---------------- cov partials: lower-tri 128x128 tiles, split-K ----------------
__global__ __launch_bounds__(256) void k_cov(const float* __restrict__ x) {
    __shared__ float As[32][132];
    __shared__ float Bs[32][132];
    const int TIa[10] = {0,1,1,2,2,2,3,3,3,3};
    const int TJa[10] = {0,0,1,0,1,2,0,1,2,3};
    int ti = TIa[blockIdx.x], tj = TJa[blockIdx.x];
    int g = blockIdx.y, sp = blockIdx.z;
    const float* Ab = x + (size_t)(g * LL + ti * 128) * NT + sp * KCH;
    const float* Bb = x + (size_t)(g * LL + tj * 128) * NT + sp * KCH;
    int t = threadIdx.x, tx = t & 15, ty = t >> 4;
    float acc[8][8];
    #pragma unroll
    for (int u = 0; u < 8; u++)
        #pragma unroll
        for (int w = 0; w < 8; w++) acc[u][w] = 0.f;
    for (int kb = 0; kb < KCH; kb += 32) {
        __syncthreads();
        #pragma unroll
        for (int q = 0; q < 4; q++) {
            int idx = t + 256 * q;
            int r = idx >> 3, c4 = (idx & 7) << 2;
            float4 av = *(const float4*)(Ab + (size_t)r * NT + kb + c4);
            As[c4][r] = av.x; As[c4+1][r] = av.y; As[c4+2][r] = av.z; As[c4+3][r] = av.w;
            float4 bv = *(const float4*)(Bb + (size_t)r * NT + kb + c4);
            Bs[c4][r] = bv.x; Bs[c4+1][r] = bv.y; Bs[c4+2][r] = bv.z; Bs[c4+3][r] = bv.w;
        }
        __syncthreads();
        #pragma unroll
        for (int k = 0; k < 32; k++) {
            float a[8], b[8];
            #pragma unroll
            for (int u = 0; u < 8; u++) { a[u] = As[k][ty*8+u]; b[u] = Bs[k][tx*8+u]; }
            #pragma unroll
            for (int u = 0; u < 8; u++)
                #pragma unroll
                for (int w = 0; w < 8; w++) acc[u][w] = fmaf(a[u], b[w], acc[u][w]);
        }
    }
    #pragma unroll
    for (int u = 0; u < 8; u++) {
        int i = ti * 128 + ty * 8 + u;
        #pragma unroll
        for (int w = 0; w < 8; w++) {
            int j = tj * 128 + tx * 8 + w;
            g_part[sp][g][i][j] = acc[u][w];
        }
    }
}

// ---------------- reduce partials -> A, mirrored full symmetric ----------------
__global__ __launch_bounds__(256) void k_cov_reduce() {
    int g = blockIdx.y;
    int idx = blockIdx.x * 256 + threadIdx.x;
    int i = idx >> 9, j = idx & 511;
    if (i < j) return;
    float s = 0.f;
    #pragma unroll
    for (int sp = 0; sp < KS; sp++) s += g_part[sp][g][i][j];
    float v = s * (1.f / NT) - g_mu[g * LL + i] * g_mu[g * LL + j];
    if (i == j) v += EPSV;
    g_A[g][i][j] = v;
    g_A[g][j][i] = v;
}

// ---------------- power iteration ----------------
__global__ void k_pi_init() {
    int idx = blockIdx.x * 256 + threadIdx.x;
    if (idx < GG * LL) {
        unsigned h = (unsigned)idx * 1103515245u + 12345u;
        ((float*)g_pv)[idx] = 0.5f + (float)(h & 1023u) * (1.0f / 1024.0f);
    }
}

__global__ __launch_bounds__(256) void k_matvec(int inb) {
    int g = blockIdx.y;
    __shared__ float vs[LL];
    for (int i = threadIdx.x; i < LL; i += 256) vs[i] = g_pv[inb][g][i];
    __syncthreads();
    int warp = threadIdx.x >> 5, lane = threadIdx.x & 31;
    int row0 = blockIdx.x * 32 + warp * 4;
    for (int r = 0; r < 4; r++) {
        int i = row0 + r;
        const float* Ar = &g_A[g][i][0];
        float s = 0.f;
        for (int k = lane; k < LL; k += 32) s += Ar[k] * vs[k];
        #pragma unroll
        for (int o = 16; o > 0; o >>= 1) s += __shfl_down_sync(0xffffffffu, s, o);
        if (lane == 0) g_pv[1 - inb][g][i] = s;
    }
}

__global__ void k_rq() {  // v=pv[0], u=pv[1]; g_scal[g]=v.u/v.v
    int g = blockIdx.x, i = threadIdx.x;
    __shared__ float r1[512], r2[512];
    float v = g_pv[0][g][i], u = g_pv[1][g][i];
    r1[i] = v * u; r2[i] = v * v; __syncthreads();
    for (int o = 256; o > 0; o >>= 1) {
        if (i < o) { r1[i] += r1[i + o]; r2[i] += r2[i + o]; }
        __syncthreads();
    }
    if (i == 0) g_scal[g] = r1[0] / r2[0];
}

// ---------------- Newton-Schulz init ----------------
__global__ __launch_bounds__(256) void k_ns_init() {
    int g = blockIdx.y;
    int idx = blockIdx.x * 256 + threadIdx.x;
    int i = idx >> 9, j = idx & 511;
    float invc = 1.0f / (1.02f * g_scal[g]);
    g_Y[0][g][i][j] = g_A[g][i][j] * invc;
    g_Z[0][g][i][j] = (i == j) ? 1.0f : 0.0f;
}

// ---------------- generic 512x512x512 GEMM ----------------
// mode 0: C = 1.5 I - 0.5 (A B)
// mode 1: C = A B
// mode 2: C = (A B) / g_fsq[iter][g]; block sumsq(C) -> g_red
__global__ __launch_bounds__(256) void k_gemm512(int ida, int idb, int idc, int mode, int iter) {
    int g = blockIdx.z;
    const float* A = bufptr(ida) + (size_t)g * LL * LL;
    const float* B = bufptr(idb) + (size_t)g * LL * LL;
    float* C = bufptr(idc) + (size_t)g * LL * LL;
    __shared__ float As[32][132];
    __shared__ float Bs[32][128];
    int t = threadIdx.x, tx = t & 15, ty = t >> 4;
    int i0 = blockIdx.y * 128, j0 = blockIdx.x * 128;
    float acc[8][8];
    #pragma unroll
    for (int u = 0; u < 8; u++)
        #pragma unroll
        for (int w = 0; w < 8; w++) acc[u][w] = 0.f;
    for (int kb = 0; kb < 512; kb += 32) {
        __syncthreads();
        #pragma unroll
        for (int q = 0; q < 4; q++) {
            int idx = t + 256 * q;
            int r = idx >> 3, c4 = (idx & 7) << 2;
            float4 av = *(const float4*)(A + (size_t)(i0 + r) * 512 + kb + c4);
            As[c4][r] = av.x; As[c4+1][r] = av.y; As[c4+2][r] = av.z; As[c4+3][r] = av.w;
            int r2 = idx >> 5, d4 = (idx & 31) << 2;
            *(float4*)(&Bs[r2][d4]) = *(const float4*)(B + (size_t)(kb + r2) * 512 + j0 + d4);
        }
        __syncthreads();
        #pragma unroll
        for (int k = 0; k < 32; k++) {
            float a[8], b[8];
            #pragma unroll
            for (int u = 0; u < 8; u++) { a[u] = As[k][ty*8+u]; b[u] = Bs[k][tx*8+u]; }
            #pragma unroll
            for (int u = 0; u < 8; u++)
                #pragma unroll
                for (int w = 0; w < 8; w++) acc[u][w] = fmaf(a[u], b[w], acc[u][w]);
        }
    }
    float scale = (mode == 2) ? (1.0f / g_fsq[iter][g]) : 1.0f;
    float ss = 0.f;
    #pragma unroll
    for (int u = 0; u < 8; u++) {
        int gi = i0 + ty * 8 + u;
        #pragma unroll
        for (int w = 0; w < 8; w++) {
            int gj = j0 + tx * 8 + w;
            float v;
            if (mode == 0)      v = (gi == gj ? 1.5f : 0.0f) - 0.5f * acc[u][w];
            else if (mode == 1) v = acc[u][w];
            else                { v = acc[u][w] * scale; ss += v * v; }
            C[(size_t)gi * 512 + gj] = v;
        }
    }
    if (mode == 2) {
        __shared__ float rs[256];
        rs[t] = ss; __syncthreads();
        for (int o = 128; o > 0; o >>= 1) { if (t < o) rs[t] += rs[t + o]; __syncthreads(); }
        if (t == 0) g_red[g][blockIdx.y * 4 + blockIdx.x] = rs[0];
    }
}

// ---------------- shifted matrix B0 = sigma I - A ----------------
__global__ __launch_bounds__(256) void k_shift() {
    int g = blockIdx.y;
    int idx = blockIdx.x * 256 + threadIdx.x;
    int i = idx >> 9, j = idx & 511;
    float sigma = 1.15f * g_scal[g];
    g_M[0][g][i][j] = (i == j ? sigma : 0.0f) - g_A[g][i][j];
}

__global__ __launch_bounds__(256) void k_fnorm0() {
    int g = blockIdx.y;
    const float* M = &g_M[0][g][0][0] + (size_t)blockIdx.x * 16384;
    float s = 0.f;
    for (int i = threadIdx.x; i < 16384; i += 256) { float m = M[i]; s += m * m; }
    __shared__ float rs[256];
    int t = threadIdx.x;
    rs[t] = s; __syncthreads();
    for (int o = 128; o > 0; o >>= 1) { if (t < o) rs[t] += rs[t + o]; __syncthreads(); }
    if (t == 0) g_red[g][blockIdx.x] = rs[0];
}

__global__ void k_comb(int iter) {
    int t = threadIdx.x;
    if (t < GG) {
        float s = 0.f;
        for (int j = 0; j < 16; j++) s += g_red[t][j];
        g_fsq[iter][t] = s;
    }
}

// ---------------- extract eigenvector (largest-norm column of final M) ----------------
__global__ void k_colnorm() {
    int g = blockIdx.x, j = threadIdx.x;
    const float* M = &g_M[0][g][0][0];
    float s = 0.f;
    for (int i = 0; i < LL; i++) { float m = M[(size_t)i * LL + j]; s += m * m; }
    __shared__ float sv[512]; __shared__ int si[512];
    sv[j] = s; si[j] = j; __syncthreads();
    for (int o = 256; o > 0; o >>= 1) {
        if (j < o) { if (sv[j + o] > sv[j]) { sv[j] = sv[j + o]; si[j] = si[j + o]; } }
        __syncthreads();
    }
    int jm = si[0];
    float inv = rsqrtf(sv[0]);
    g_v[g][j] = M[(size_t)j * LL + jm] * inv;
}

__global__ void k_rayleigh() {
    int g = blockIdx.x, i = threadIdx.x;
    __shared__ float vs[512];
    vs[i] = g_v[g][i]; __syncthreads();
    float u = 0.f;
    const float* Ar = &g_A[g][i][0];
    for (int k = 0; k < 512; k++) u += Ar[k] * vs[k];
    __shared__ float r1[512], r2[512];
    r1[i] = u * vs[i]; r2[i] = vs[i] * vs[i]; __syncthreads();
    for (int o = 256; o > 0; o >>= 1) {
        if (i < o) { r1[i] += r1[i + o]; r2[i] += r2[i + o]; }
        __syncthreads();
    }
    if (i == 0) g_scal[8 + g] = r1[0] / r2[0];
}

// ---------------- P = Z/sqrt(c) - lam^{-1/2} v v^T ----------------
__global__ __launch_bounds__(256) void k_subspace(int zid) {
    int g = blockIdx.y;
    int idx = blockIdx.x * 256 + threadIdx.x;
    int i = idx >> 9, j = idx & 511;
    const float* Z = bufptr(zid) + (size_t)g * LL * LL;
    float c = 1.02f * g_scal[g];
    float lam = g_scal[8 + g];
    g_P[g][i][j] = Z[(size_t)i * 512 + j] * rsqrtf(c) - rsqrtf(lam) * g_v[g][i] * g_v[g][j];
}

// ---------------- beta = bias - w * (P mu) ----------------
__global__ void k_beta(const float* __restrict__ w, const float* __restrict__ b) {
    int g = blockIdx.x, i = threadIdx.x;
    __shared__ float mus[512];
    mus[i] = g_mu[g * LL + i]; __syncthreads();
    float s = 0.f;
    const float* Pr = &g_P[g][i][0];
    for (int k = 0; k < 512; k++) s += Pr[k] * mus[k];
    int c = g * LL + i;
    g_beta[c] = b[c] - w[c] * s;
}

// ---------------- apply: out = w * (P X) + beta ----------------
__global__ __launch_bounds__(256) void k_apply(const float* __restrict__ x,
                                               const float* __restrict__ w,
                                               float* __restrict__ out) {
    int g = blockIdx.z;
    int i0 = blockIdx.y * 128;
    int j0 = blockIdx.x * 128;
    __shared__ float As[32][132];
    __shared__ float Bs[32][128];
    int t = threadIdx.x, tx = t & 15, ty = t >> 4;
    const float* P = &g_P[g][0][0];
    float acc[8][8];
    #pragma unroll
    for (int u = 0; u < 8; u++)
        #pragma unroll
        for (int wv = 0; wv < 8; wv++) acc[u][wv] = 0.f;
    for (int kb = 0; kb < 512; kb += 32) {
        __syncthreads();
        #pragma unroll
        for (int q = 0; q < 4; q++) {
            int idx = t + 256 * q;
            int r = idx >> 3, c4 = (idx & 7) << 2;
            float4 av = *(const float4*)(P + (size_t)(i0 + r) * 512 + kb + c4);
            As[c4][r] = av.x; As[c4+1][r] = av.y; As[c4+2][r] = av.z; As[c4+3][r] = av.w;
            int r2 = idx >> 5, d4 = (idx & 31) << 2;
            *(float4*)(&Bs[r2][d4]) =
                *(const float4*)(x + (size_t)(g * LL + kb + r2) * NT + j0 + d4);
        }
        __syncthreads();
        #pragma unroll
        for (int k = 0; k < 32; k++) {
            float a[8], bb[8];
            #pragma unroll
            for (int u = 0; u < 8; u++) { a[u] = As[k][ty*8+u]; bb[u] = Bs[k][tx*8+u]; }
            #pragma unroll
            for (int u = 0; u < 8; u++)
                #pragma unroll
                for (int wv = 0; wv < 8; wv++) acc[u][wv] = fmaf(a[u], bb[wv], acc[u][wv]);
        }
    }
    #pragma unroll
    for (int u = 0; u < 8; u++) {
        int ch = g * LL + i0 + ty * 8 + u;
        float wc = w[ch], bc = g_beta[ch];
        float* orow = out + (size_t)ch * NT + j0 + tx * 8;
        float4 v0, v1;
        v0.x = fmaf(wc, acc[u][0], bc); v0.y = fmaf(wc, acc[u][1], bc);
        v0.z = fmaf(wc, acc[u][2], bc); v0.w = fmaf(wc, acc[u][3], bc);
        v1.x = fmaf(wc, acc[u][4], bc); v1.y = fmaf(wc, acc[u][5], bc);
        v1.z = fmaf(wc, acc[u][6], bc); v1.w = fmaf(wc, acc[u][7], bc);
        *(float4*)(orow) = v0;
        *(float4*)(orow + 4) = v1;
    }
}

// ---------------- launch ----------------
extern "C" void kernel_launch(void* const* d_in, const int* in_sizes, int n_in,
                              void* d_out, int out_size) {
    const float* x = (const float*)d_in[0];
    const float* w = (const float*)d_in[1];
    const float* b = (const float*)d_in[2];
    float* out = (float*)d_out;

    k_mean<<<CC, 256>>>(x);
    k_cov<<<dim3(10, GG, KS), 256>>>(x);
    k_cov_reduce<<<dim3(1024, GG), 256>>>();

    k_pi_init<<<8, 256>>>();
    for (int m = 0; m < 11; m++)
        k_matvec<<<dim3(16, GG), 256>>>(m & 1);
    k_rq<<<GG, 512>>>();

    k_ns_init<<<dim3(1024, GG), 256>>>();
    int yc = 0, zc = 0;
    for (int it = 0; it < NS_ITERS; it++) {
        k_gemm512<<<dim3(4, 4, GG), 256>>>(2 + zc, 0 + yc, 4, 0, 0);      // T = 1.5I - 0.5 Z Y
        k_gemm512<<<dim3(4, 4, GG), 256>>>(0 + yc, 4, 1 - yc, 1, 0);      // Y' = Y T
        k_gemm512<<<dim3(4, 4, GG), 256>>>(4, 2 + zc, 2 + (1 - zc), 1, 0);// Z' = T Z
        yc ^= 1; zc ^= 1;
    }

    k_shift<<<dim3(1024, GG), 256>>>();
    k_fnorm0<<<dim3(16, GG), 256>>>();
    k_comb<<<1, 32>>>(0);
    for (int k = 0; k < SQ_ITERS; k++) {
        int inb = 5 + (k & 1), outb = 5 + (1 - (k & 1));
        k_gemm512<<<dim3(4, 4, GG), 256>>>(inb, inb, outb, 2, k);
        k_comb<<<1, 32>>>(k + 1);
    }

    k_colnorm<<<GG, 512>>>();
    k_rayleigh<<<GG, 512>>>();
    k_subspace<<<dim3(1024, GG), 256>>>(2 + zc);
    k_beta<<<GG, 512>>>(w, b);
    k_apply<<<dim3(128, 4, GG), 256>>>(x, w, out);
}

// round 4
// speedup vs baseline: 1.0017x; 1.0017x over previous
#include <cuda_runtime.h>
#include <cuda_bf16.h>
#include <math.h>

#define CC 2048
#define GG 4
#define LL 512
#define NT 16384
#define EPSV 1e-4f
#define KS 16
#define KCH (NT/KS)
#define NS_ITERS 5
#define SQ_ITERS 16

// ---------------- device scratch (static, no allocations) ----------------
__device__ float g_part[KS][GG][LL][LL];   // cov split-K partials
__device__ float g_A[GG][LL][LL];          // covariance + eps I (full symmetric)
__device__ float g_Y[2][GG][LL][LL];
__device__ float g_Z[2][GG][LL][LL];
__device__ float g_T[GG][LL][LL];
__device__ float g_M[2][GG][LL][LL];       // squaring ping-pong
__device__ float g_P[GG][LL][LL];          // final subspace
__device__ float g_mu[CC];
__device__ float g_pv[2][GG][LL];          // power-iteration vectors
__device__ float g_v[GG][LL];              // smallest eigenvector
__device__ float g_beta[CC];
__device__ float g_scal[16];               // [g]=RQ(lam_max est), [8+g]=lam_min
__device__ float g_fsq[SQ_ITERS + 1][GG];  // Frobenius^2 chain
__device__ float g_red[GG][16];            // per-tile partials

__device__ __forceinline__ float* bufptr(int id) {
    switch (id) {
        case 0: return &g_Y[0][0][0][0];
        case 1: return &g_Y[1][0][0][0];
        case 2: return &g_Z[0][0][0][0];
        case 3: return &g_Z[1][0][0][0];
        case 4: return &g_T[0][0][0];
        case 5: return &g_M[0][0][0][0];
        case 6: return &g_M[1][0][0][0];
        default: return &g_A[0][0][0];
    }
}

// ---------------- per-channel mean ----------------
__global__ __launch_bounds__(256) void k_mean(const float* __restrict__ x) {
    __shared__ float sm[256];
    int c = blockIdx.x;
    const float4* row = (const float4*)(x + (size_t)c * NT);
    float s = 0.f;
    for (int i = threadIdx.x; i < NT / 4; i += 256) {
        float4 v = row[i];
        s += (v.x + v.y) + (v.z + v.w);
    }
    int t = threadIdx.x;
    sm[t] = s; __syncthreads();
    for (int o = 128; o > 0; o >>= 1) { if (t < o) sm[t] += sm[t + o]; __syncthreads(); }
    if (t == 0) g_mu[c] = sm[0] * (1.f / NT);
}

// ---------------- cov partials: lower-tri 128x128 tiles, split-K ----------------
__global__ __launch_bounds__(256) void k_cov(const float* __restrict__ x) {
    __shared__ float As[32][132];
    __shared__ float Bs[32][132];
    const int TIa[10] = {0,1,1,2,2,2,3,3,3,3};
    const int TJa[10] = {0,0,1,0,1,2,0,1,2,3};
    int ti = TIa[blockIdx.x], tj = TJa[blockIdx.x];
    int g = blockIdx.y, sp = blockIdx.z;
    const float* Ab = x + (size_t)(g * LL + ti * 128) * NT + sp * KCH;
    const float* Bb = x + (size_t)(g * LL + tj * 128) * NT + sp * KCH;
    int t = threadIdx.x, tx = t & 15, ty = t >> 4;
    float acc[8][8];
    #pragma unroll
    for (int u = 0; u < 8; u++)
        #pragma unroll
        for (int w = 0; w < 8; w++) acc[u][w] = 0.f;
    for (int kb = 0; kb < KCH; kb += 32) {
        __syncthreads();
        #pragma unroll
        for (int q = 0; q < 4; q++) {
            int idx = t + 256 * q;
            int r = idx >> 3, c4 = (idx & 7) << 2;
            float4 av = *(const float4*)(Ab + (size_t)r * NT + kb + c4);
            As[c4][r] = av.x; As[c4+1][r] = av.y; As[c4+2][r] = av.z; As[c4+3][r] = av.w;
            float4 bv = *(const float4*)(Bb + (size_t)r * NT + kb + c4);
            Bs[c4][r] = bv.x; Bs[c4+1][r] = bv.y; Bs[c4+2][r] = bv.z; Bs[c4+3][r] = bv.w;
        }
        __syncthreads();
        #pragma unroll
        for (int k = 0; k < 32; k++) {
            float a[8], b[8];
            #pragma unroll
            for (int u = 0; u < 8; u++) { a[u] = As[k][ty*8+u]; b[u] = Bs[k][tx*8+u]; }
            #pragma unroll
            for (int u = 0; u < 8; u++)
                #pragma unroll
                for (int w = 0; w < 8; w++) acc[u][w] = fmaf(a[u], b[w], acc[u][w]);
        }
    }
    #pragma unroll
    for (int u = 0; u < 8; u++) {
        int i = ti * 128 + ty * 8 + u;
        #pragma unroll
        for (int w = 0; w < 8; w++) {
            int j = tj * 128 + tx * 8 + w;
            g_part[sp][g][i][j] = acc[u][w];
        }
    }
}

// ---------------- reduce partials -> A, mirrored full symmetric ----------------
__global__ __launch_bounds__(256) void k_cov_reduce() {
    int g = blockIdx.y;
    int idx = blockIdx.x * 256 + threadIdx.x;
    int i = idx >> 9, j = idx & 511;
    if (i < j) return;
    float s = 0.f;
    #pragma unroll
    for (int sp = 0; sp < KS; sp++) s += g_part[sp][g][i][j];
    float v = s * (1.f / NT) - g_mu[g * LL + i] * g_mu[g * LL + j];
    if (i == j) v += EPSV;
    g_A[g][i][j] = v;
    g_A[g][j][i] = v;
}

// ---------------- power iteration ----------------
__global__ void k_pi_init() {
    int idx = blockIdx.x * 256 + threadIdx.x;
    if (idx < GG * LL) {
        unsigned h = (unsigned)idx * 1103515245u + 12345u;
        ((float*)g_pv)[idx] = 0.5f + (float)(h & 1023u) * (1.0f / 1024.0f);
    }
}

__global__ __launch_bounds__(256) void k_matvec(int inb) {
    int g = blockIdx.y;
    __shared__ float vs[LL];
    for (int i = threadIdx.x; i < LL; i += 256) vs[i] = g_pv[inb][g][i];
    __syncthreads();
    int warp = threadIdx.x >> 5, lane = threadIdx.x & 31;
    int row0 = blockIdx.x * 32 + warp * 4;
    for (int r = 0; r < 4; r++) {
        int i = row0 + r;
        const float* Ar = &g_A[g][i][0];
        float s = 0.f;
        for (int k = lane; k < LL; k += 32) s += Ar[k] * vs[k];
        #pragma unroll
        for (int o = 16; o > 0; o >>= 1) s += __shfl_down_sync(0xffffffffu, s, o);
        if (lane == 0) g_pv[1 - inb][g][i] = s;
    }
}

__global__ void k_rq() {  // v=pv[0], u=pv[1]; g_scal[g]=v.u/v.v
    int g = blockIdx.x, i = threadIdx.x;
    __shared__ float r1[512], r2[512];
    float v = g_pv[0][g][i], u = g_pv[1][g][i];
    r1[i] = v * u; r2[i] = v * v; __syncthreads();
    for (int o = 256; o > 0; o >>= 1) {
        if (i < o) { r1[i] += r1[i + o]; r2[i] += r2[i + o]; }
        __syncthreads();
    }
    if (i == 0) g_scal[g] = r1[0] / r2[0];
}

// ---------------- Newton-Schulz init ----------------
__global__ __launch_bounds__(256) void k_ns_init() {
    int g = blockIdx.y;
    int idx = blockIdx.x * 256 + threadIdx.x;
    int i = idx >> 9, j = idx & 511;
    float invc = 1.0f / (1.02f * g_scal[g]);
    g_Y[0][g][i][j] = g_A[g][i][j] * invc;
    g_Z[0][g][i][j] = (i == j) ? 1.0f : 0.0f;
}

// ---------------- generic 512x512x512 GEMM ----------------
// mode 0: C = 1.5 I - 0.5 (A B)
// mode 1: C = A B
// mode 2: C = (A B) / g_fsq[iter][g]; block sumsq(C) -> g_red
__global__ __launch_bounds__(256) void k_gemm512(int ida, int idb, int idc, int mode, int iter) {
    int g = blockIdx.z;
    const float* A = bufptr(ida) + (size_t)g * LL * LL;
    const float* B = bufptr(idb) + (size_t)g * LL * LL;
    float* C = bufptr(idc) + (size_t)g * LL * LL;
    __shared__ float As[32][132];
    __shared__ float Bs[32][128];
    int t = threadIdx.x, tx = t & 15, ty = t >> 4;
    int i0 = blockIdx.y * 128, j0 = blockIdx.x * 128;
    float acc[8][8];
    #pragma unroll
    for (int u = 0; u < 8; u++)
        #pragma unroll
        for (int w = 0; w < 8; w++) acc[u][w] = 0.f;
    for (int kb = 0; kb < 512; kb += 32) {
        __syncthreads();
        #pragma unroll
        for (int q = 0; q < 4; q++) {
            int idx = t + 256 * q;
            int r = idx >> 3, c4 = (idx & 7) << 2;
            float4 av = *(const float4*)(A + (size_t)(i0 + r) * 512 + kb + c4);
            As[c4][r] = av.x; As[c4+1][r] = av.y; As[c4+2][r] = av.z; As[c4+3][r] = av.w;
            int r2 = idx >> 5, d4 = (idx & 31) << 2;
            *(float4*)(&Bs[r2][d4]) = *(const float4*)(B + (size_t)(kb + r2) * 512 + j0 + d4);
        }
        __syncthreads();
        #pragma unroll
        for (int k = 0; k < 32; k++) {
            float a[8], b[8];
            #pragma unroll
            for (int u = 0; u < 8; u++) { a[u] = As[k][ty*8+u]; b[u] = Bs[k][tx*8+u]; }
            #pragma unroll
            for (int u = 0; u < 8; u++)
                #pragma unroll
                for (int w = 0; w < 8; w++) acc[u][w] = fmaf(a[u], b[w], acc[u][w]);
        }
    }
    float scale = (mode == 2) ? (1.0f / g_fsq[iter][g]) : 1.0f;
    float ss = 0.f;
    #pragma unroll
    for (int u = 0; u < 8; u++) {
        int gi = i0 + ty * 8 + u;
        #pragma unroll
        for (int w = 0; w < 8; w++) {
            int gj = j0 + tx * 8 + w;
            float v;
            if (mode == 0)      v = (gi == gj ? 1.5f : 0.0f) - 0.5f * acc[u][w];
            else if (mode == 1) v = acc[u][w];
            else                { v = acc[u][w] * scale; ss += v * v; }
            C[(size_t)gi * 512 + gj] = v;
        }
    }
    if (mode == 2) {
        __shared__ float rs[256];
        rs[t] = ss; __syncthreads();
        for (int o = 128; o > 0; o >>= 1) { if (t < o) rs[t] += rs[t + o]; __syncthreads(); }
        if (t == 0) g_red[g][blockIdx.y * 4 + blockIdx.x] = rs[0];
    }
}

// ---------------- shifted matrix B0 = sigma I - A ----------------
__global__ __launch_bounds__(256) void k_shift() {
    int g = blockIdx.y;
    int idx = blockIdx.x * 256 + threadIdx.x;
    int i = idx >> 9, j = idx & 511;
    float sigma = 1.15f * g_scal[g];
    g_M[0][g][i][j] = (i == j ? sigma : 0.0f) - g_A[g][i][j];
}

__global__ __launch_bounds__(256) void k_fnorm0() {
    int g = blockIdx.y;
    const float* M = &g_M[0][g][0][0] + (size_t)blockIdx.x * 16384;
    float s = 0.f;
    for (int i = threadIdx.x; i < 16384; i += 256) { float m = M[i]; s += m * m; }
    __shared__ float rs[256];
    int t = threadIdx.x;
    rs[t] = s; __syncthreads();
    for (int o = 128; o > 0; o >>= 1) { if (t < o) rs[t] += rs[t + o]; __syncthreads(); }
    if (t == 0) g_red[g][blockIdx.x] = rs[0];
}

__global__ void k_comb(int iter) {
    int t = threadIdx.x;
    if (t < GG) {
        float s = 0.f;
        for (int j = 0; j < 16; j++) s += g_red[t][j];
        g_fsq[iter][t] = s;
    }
}

// ---------------- extract eigenvector (largest-norm column of final M) ----------------
__global__ void k_colnorm() {
    int g = blockIdx.x, j = threadIdx.x;
    const float* M = &g_M[0][g][0][0];
    float s = 0.f;
    for (int i = 0; i < LL; i++) { float m = M[(size_t)i * LL + j]; s += m * m; }
    __shared__ float sv[512]; __shared__ int si[512];
    sv[j] = s; si[j] = j; __syncthreads();
    for (int o = 256; o > 0; o >>= 1) {
        if (j < o) { if (sv[j + o] > sv[j]) { sv[j] = sv[j + o]; si[j] = si[j + o]; } }
        __syncthreads();
    }
    int jm = si[0];
    float inv = rsqrtf(sv[0]);
    g_v[g][j] = M[(size_t)j * LL + jm] * inv;
}

__global__ void k_rayleigh() {
    int g = blockIdx.x, i = threadIdx.x;
    __shared__ float vs[512];
    vs[i] = g_v[g][i]; __syncthreads();
    float u = 0.f;
    const float* Ar = &g_A[g][i][0];
    for (int k = 0; k < 512; k++) u += Ar[k] * vs[k];
    __shared__ float r1[512], r2[512];
    r1[i] = u * vs[i]; r2[i] = vs[i] * vs[i]; __syncthreads();
    for (int o = 256; o > 0; o >>= 1) {
        if (i < o) { r1[i] += r1[i + o]; r2[i] += r2[i + o]; }
        __syncthreads();
    }
    if (i == 0) g_scal[8 + g] = r1[0] / r2[0];
}

// ---------------- P = Z/sqrt(c) - lam^{-1/2} v v^T ----------------
__global__ __launch_bounds__(256) void k_subspace(int zid) {
    int g = blockIdx.y;
    int idx = blockIdx.x * 256 + threadIdx.x;
    int i = idx >> 9, j = idx & 511;
    const float* Z = bufptr(zid) + (size_t)g * LL * LL;
    float c = 1.02f * g_scal[g];
    float lam = g_scal[8 + g];
    g_P[g][i][j] = Z[(size_t)i * 512 + j] * rsqrtf(c) - rsqrtf(lam) * g_v[g][i] * g_v[g][j];
}

// ---------------- beta = bias - w * (P mu) ----------------
__global__ void k_beta(const float* __restrict__ w, const float* __restrict__ b) {
    int g = blockIdx.x, i = threadIdx.x;
    __shared__ float mus[512];
    mus[i] = g_mu[g * LL + i]; __syncthreads();
    float s = 0.f;
    const float* Pr = &g_P[g][i][0];
    for (int k = 0; k < 512; k++) s += Pr[k] * mus[k];
    int c = g * LL + i;
    g_beta[c] = b[c] - w[c] * s;
}

// ---------------- apply: out = w * (P X) + beta ----------------
__global__ __launch_bounds__(256) void k_apply(const float* __restrict__ x,
                                               const float* __restrict__ w,
                                               float* __restrict__ out) {
    int g = blockIdx.z;
    int i0 = blockIdx.y * 128;
    int j0 = blockIdx.x * 128;
    __shared__ float As[32][132];
    __shared__ float Bs[32][128];
    int t = threadIdx.x, tx = t & 15, ty = t >> 4;
    const float* P = &g_P[g][0][0];
    float acc[8][8];
    #pragma unroll
    for (int u = 0; u < 8; u++)
        #pragma unroll
        for (int wv = 0; wv < 8; wv++) acc[u][wv] = 0.f;
    for (int kb = 0; kb < 512; kb += 32) {
        __syncthreads();
        #pragma unroll
        for (int q = 0; q < 4; q++) {
            int idx = t + 256 * q;
            int r = idx >> 3, c4 = (idx & 7) << 2;
            float4 av = *(const float4*)(P + (size_t)(i0 + r) * 512 + kb + c4);
            As[c4][r] = av.x; As[c4+1][r] = av.y; As[c4+2][r] = av.z; As[c4+3][r] = av.w;
            int r2 = idx >> 5, d4 = (idx & 31) << 2;
            *(float4*)(&Bs[r2][d4]) =
                *(const float4*)(x + (size_t)(g * LL + kb + r2) * NT + j0 + d4);
        }
        __syncthreads();
        #pragma unroll
        for (int k = 0; k < 32; k++) {
            float a[8], bb[8];
            #pragma unroll
            for (int u = 0; u < 8; u++) { a[u] = As[k][ty*8+u]; bb[u] = Bs[k][tx*8+u]; }
            #pragma unroll
            for (int u = 0; u < 8; u++)
                #pragma unroll
                for (int wv = 0; wv < 8; wv++) acc[u][wv] = fmaf(a[u], bb[wv], acc[u][wv]);
        }
    }
    #pragma unroll
    for (int u = 0; u < 8; u++) {
        int ch = g * LL + i0 + ty * 8 + u;
        float wc = w[ch], bc = g_beta[ch];
        float* orow = out + (size_t)ch * NT + j0 + tx * 8;
        float4 v0, v1;
        v0.x = fmaf(wc, acc[u][0], bc); v0.y = fmaf(wc, acc[u][1], bc);
        v0.z = fmaf(wc, acc[u][2], bc); v0.w = fmaf(wc, acc[u][3], bc);
        v1.x = fmaf(wc, acc[u][4], bc); v1.y = fmaf(wc, acc[u][5], bc);
        v1.z = fmaf(wc, acc[u][6], bc); v1.w = fmaf(wc, acc[u][7], bc);
        *(float4*)(orow) = v0;
        *(float4*)(orow + 4) = v1;
    }
}

// ---------------- launch ----------------
extern "C" void kernel_launch(void* const* d_in, const int* in_sizes, int n_in,
                              void* d_out, int out_size) {
    const float* x = (const float*)d_in[0];
    const float* w = (const float*)d_in[1];
    const float* b = (const float*)d_in[2];
    float* out = (float*)d_out;

    k_mean<<<CC, 256>>>(x);
    k_cov<<<dim3(10, GG, KS), 256>>>(x);
    k_cov_reduce<<<dim3(1024, GG), 256>>>();

    k_pi_init<<<8, 256>>>();
    for (int m = 0; m < 11; m++)
        k_matvec<<<dim3(16, GG), 256>>>(m & 1);
    k_rq<<<GG, 512>>>();

    k_ns_init<<<dim3(1024, GG), 256>>>();
    int yc = 0, zc = 0;
    for (int it = 0; it < NS_ITERS; it++) {
        k_gemm512<<<dim3(4, 4, GG), 256>>>(2 + zc, 0 + yc, 4, 0, 0);      // T = 1.5I - 0.5 Z Y
        k_gemm512<<<dim3(4, 4, GG), 256>>>(0 + yc, 4, 1 - yc, 1, 0);      // Y' = Y T
        k_gemm512<<<dim3(4, 4, GG), 256>>>(4, 2 + zc, 2 + (1 - zc), 1, 0);// Z' = T Z
        yc ^= 1; zc ^= 1;
    }

    k_shift<<<dim3(1024, GG), 256>>>();
    k_fnorm0<<<dim3(16, GG), 256>>>();
    k_comb<<<1, 32>>>(0);
    for (int k = 0; k < SQ_ITERS; k++) {
        int inb = 5 + (k & 1), outb = 5 + (1 - (k & 1));
        k_gemm512<<<dim3(4, 4, GG), 256>>>(inb, inb, outb, 2, k);
        k_comb<<<1, 32>>>(k + 1);
    }

    k_colnorm<<<GG, 512>>>();
    k_rayleigh<<<GG, 512>>>();
    k_subspace<<<dim3(1024, GG), 256>>>(2 + zc);
    k_beta<<<GG, 512>>>(w, b);
    k_apply<<<dim3(128, 4, GG), 256>>>(x, w, out);
}

// round 5
// speedup vs baseline: 1.8310x; 1.8279x over previous
#include <cuda_runtime.h>
#include <cuda_bf16.h>
#include <math.h>

#define CC 2048
#define GG 4
#define LL 512
#define NT 16384
#define EPSV 1e-4f
#define KS 16
#define KCH (NT/KS)
#define SQ_ITERS 12

typedef unsigned long long u64;

__device__ __forceinline__ u64 ffma2(u64 a, u64 b, u64 c) {
    u64 d;
    asm("fma.rn.f32x2 %0, %1, %2, %3;" : "=l"(d) : "l"(a), "l"(b), "l"(c));
    return d;
}
__device__ __forceinline__ u64 splat2(float x) {
    u64 d; unsigned xi = __float_as_uint(x);
    asm("mov.b64 %0, {%1, %2};" : "=l"(d) : "r"(xi), "r"(xi));
    return d;
}
__device__ __forceinline__ float2 unpk(u64 v) {
    unsigned lo, hi;
    asm("mov.b64 {%0, %1}, %2;" : "=r"(lo), "=r"(hi) : "l"(v));
    float2 r; r.x = __uint_as_float(lo); r.y = __uint_as_float(hi); return r;
}

// ---------------- device scratch ----------------
__device__ float g_part[KS][GG][LL][LL];
__device__ float g_A[GG][LL][LL];
__device__ float g_Y[2][GG][LL][LL];
__device__ float g_Z[2][GG][LL][LL];
__device__ float g_T[GG][LL][LL];
__device__ float g_M[2][GG][LL][LL];
__device__ float g_P[GG][LL][LL];
__device__ float g_mu[CC];
__device__ float g_pv[2][GG][LL];
__device__ float g_v[GG][LL];
__device__ float g_beta[CC];
__device__ float g_scal[16];          // [g]=RQ lam_max est, [8+g]=lam_min
__device__ float g_red2[2][GG][32];   // Frobenius^2 partials, ping-pong

__device__ __forceinline__ float* bufptr(int id) {
    switch (id) {
        case 0: return &g_Y[0][0][0][0];
        case 1: return &g_Y[1][0][0][0];
        case 2: return &g_Z[0][0][0][0];
        case 3: return &g_Z[1][0][0][0];
        case 4: return &g_T[0][0][0];
        case 5: return &g_M[0][0][0][0];
        case 6: return &g_M[1][0][0][0];
        default: return &g_A[0][0][0];
    }
}

// ---------------- per-channel mean ----------------
__global__ __launch_bounds__(256) void k_mean(const float* __restrict__ x) {
    __shared__ float sm[256];
    int c = blockIdx.x;
    const float4* row = (const float4*)(x + (size_t)c * NT);
    float s = 0.f;
    for (int i = threadIdx.x; i < NT / 4; i += 256) {
        float4 v = row[i];
        s += (v.x + v.y) + (v.z + v.w);
    }
    int t = threadIdx.x;
    sm[t] = s; __syncthreads();
    for (int o = 128; o > 0; o >>= 1) { if (t < o) sm[t] += sm[t + o]; __syncthreads(); }
    if (t == 0) g_mu[c] = sm[0] * (1.f / NT);
}

// ---------------- cov partials: lower-tri 128x128 tiles, split-K, FFMA2 ----------------
__global__ __launch_bounds__(256) void k_cov(const float* __restrict__ x) {
    __shared__ float As[32][132];
    __shared__ float Bs[32][132];
    const int TIa[10] = {0,1,1,2,2,2,3,3,3,3};
    const int TJa[10] = {0,0,1,0,1,2,0,1,2,3};
    int ti = TIa[blockIdx.x], tj = TJa[blockIdx.x];
    int g = blockIdx.y, sp = blockIdx.z;
    const float* Ab = x + (size_t)(g * LL + ti * 128) * NT + sp * KCH;
    const float* Bb = x + (size_t)(g * LL + tj * 128) * NT + sp * KCH;
    int t = threadIdx.x, tx = t & 15, ty = t >> 4;
    u64 acc[4][8];
    #pragma unroll
    for (int u = 0; u < 4; u++)
        #pragma unroll
        for (int w = 0; w < 8; w++) acc[u][w] = 0ull;
    for (int kb = 0; kb < KCH; kb += 32) {
        __syncthreads();
        #pragma unroll
        for (int q = 0; q < 4; q++) {
            int idx = t + 256 * q;
            int r = idx >> 3, c4 = (idx & 7) << 2;
            float4 av = *(const float4*)(Ab + (size_t)r * NT + kb + c4);
            As[c4][r] = av.x; As[c4+1][r] = av.y; As[c4+2][r] = av.z; As[c4+3][r] = av.w;
            float4 bv = *(const float4*)(Bb + (size_t)r * NT + kb + c4);
            Bs[c4][r] = bv.x; Bs[c4+1][r] = bv.y; Bs[c4+2][r] = bv.z; Bs[c4+3][r] = bv.w;
        }
        __syncthreads();
        #pragma unroll
        for (int k = 0; k < 32; k++) {
            ulonglong2 a0 = *(const ulonglong2*)&As[k][ty * 8];
            ulonglong2 a1 = *(const ulonglong2*)&As[k][ty * 8 + 4];
            float4 b0 = *(const float4*)&Bs[k][tx * 8];
            float4 b1 = *(const float4*)&Bs[k][tx * 8 + 4];
            u64 s0 = splat2(b0.x), s1 = splat2(b0.y), s2 = splat2(b0.z), s3 = splat2(b0.w);
            u64 s4 = splat2(b1.x), s5 = splat2(b1.y), s6 = splat2(b1.z), s7 = splat2(b1.w);
            u64 ar[4] = {a0.x, a0.y, a1.x, a1.y};
            #pragma unroll
            for (int u = 0; u < 4; u++) {
                acc[u][0] = ffma2(ar[u], s0, acc[u][0]);
                acc[u][1] = ffma2(ar[u], s1, acc[u][1]);
                acc[u][2] = ffma2(ar[u], s2, acc[u][2]);
                acc[u][3] = ffma2(ar[u], s3, acc[u][3]);
                acc[u][4] = ffma2(ar[u], s4, acc[u][4]);
                acc[u][5] = ffma2(ar[u], s5, acc[u][5]);
                acc[u][6] = ffma2(ar[u], s6, acc[u][6]);
                acc[u][7] = ffma2(ar[u], s7, acc[u][7]);
            }
        }
    }
    #pragma unroll
    for (int u = 0; u < 4; u++) {
        int ia = ti * 128 + ty * 8 + 2 * u;
        int jb = tj * 128 + tx * 8;
        float2 f[8];
        #pragma unroll
        for (int w = 0; w < 8; w++) f[w] = unpk(acc[u][w]);
        float4 lo0 = make_float4(f[0].x, f[1].x, f[2].x, f[3].x);
        float4 lo1 = make_float4(f[4].x, f[5].x, f[6].x, f[7].x);
        float4 hi0 = make_float4(f[0].y, f[1].y, f[2].y, f[3].y);
        float4 hi1 = make_float4(f[4].y, f[5].y, f[6].y, f[7].y);
        *(float4*)&g_part[sp][g][ia][jb]     = lo0;
        *(float4*)&g_part[sp][g][ia][jb + 4] = lo1;
        *(float4*)&g_part[sp][g][ia + 1][jb]     = hi0;
        *(float4*)&g_part[sp][g][ia + 1][jb + 4] = hi1;
    }
}

// ---------------- reduce partials -> A ----------------
__global__ __launch_bounds__(256) void k_cov_reduce() {
    int g = blockIdx.y;
    int idx = blockIdx.x * 256 + threadIdx.x;
    int i = idx >> 9, j = idx & 511;
    if (i < j) return;
    float s = 0.f;
    #pragma unroll
    for (int sp = 0; sp < KS; sp++) s += g_part[sp][g][i][j];
    float v = s * (1.f / NT) - g_mu[g * LL + i] * g_mu[g * LL + j];
    if (i == j) v += EPSV;
    g_A[g][i][j] = v;
    g_A[g][j][i] = v;
}

// ---------------- power iteration ----------------
__global__ void k_pi_init() {
    int idx = blockIdx.x * 256 + threadIdx.x;
    if (idx < GG * LL) {
        unsigned h = (unsigned)idx * 1103515245u + 12345u;
        ((float*)g_pv)[idx] = 0.5f + (float)(h & 1023u) * (1.0f / 1024.0f);
    }
}

__global__ __launch_bounds__(256) void k_matvec(int inb) {
    int g = blockIdx.y;
    __shared__ float vs[LL];
    for (int i = threadIdx.x; i < LL; i += 256) vs[i] = g_pv[inb][g][i];
    __syncthreads();
    int warp = threadIdx.x >> 5, lane = threadIdx.x & 31;
    int row0 = blockIdx.x * 32 + warp * 4;
    for (int r = 0; r < 4; r++) {
        int i = row0 + r;
        const float* Ar = &g_A[g][i][0];
        float s = 0.f;
        for (int k = lane; k < LL; k += 32) s += Ar[k] * vs[k];
        #pragma unroll
        for (int o = 16; o > 0; o >>= 1) s += __shfl_down_sync(0xffffffffu, s, o);
        if (lane == 0) g_pv[1 - inb][g][i] = s;
    }
}

__global__ void k_rq() {
    int g = blockIdx.x, i = threadIdx.x;
    __shared__ float r1[512], r2[512];
    float v = g_pv[0][g][i], u = g_pv[1][g][i];
    r1[i] = v * u; r2[i] = v * v; __syncthreads();
    for (int o = 256; o > 0; o >>= 1) {
        if (i < o) { r1[i] += r1[i + o]; r2[i] += r2[i + o]; }
        __syncthreads();
    }
    if (i == 0) g_scal[g] = r1[0] / r2[0];
}

// ---------------- NS init: Y0 = A/c, Z0slot <- T0 = 1.5I - 0.5 Y0 ----------------
__global__ __launch_bounds__(256) void k_ns_init() {
    int g = blockIdx.y;
    int idx = blockIdx.x * 256 + threadIdx.x;
    int i = idx >> 9, j = idx & 511;
    float invc = 1.0f / (1.05f * g_scal[g]);
    float y = g_A[g][i][j] * invc;
    g_Y[0][g][i][j] = y;
    g_Z[0][g][i][j] = (i == j ? 1.5f : 0.0f) - 0.5f * y;
}

// ---------------- 512x512x512 GEMM, 128x64 tiles, FFMA2 ----------------
// mode 0: C = 1.5 I - 0.5 (A B)
// mode 1: C = A B
// mode 2: C = (A B) * rsqrt(sum g_red2[rs]); block sumsq -> g_red2[ws]
__global__ __launch_bounds__(256) void k_gemm512(int ida, int idb, int idc,
                                                 int mode, int rs, int ws) {
    int g = blockIdx.z;
    const float* A = bufptr(ida) + (size_t)g * LL * LL;
    const float* B = bufptr(idb) + (size_t)g * LL * LL;
    float* C = bufptr(idc) + (size_t)g * LL * LL;
    __shared__ float As[32][132];
    __shared__ float Bs[32][68];
    __shared__ float rsm[256];
    int t = threadIdx.x, tx = t & 15, ty = t >> 4;
    int i0 = blockIdx.y * 128, j0 = blockIdx.x * 64;
    float scale = 1.0f;
    if (mode == 2) {
        float fs = 0.f;
        #pragma unroll
        for (int q = 0; q < 32; q++) fs += g_red2[rs][g][q];
        scale = rsqrtf(fs);
    }
    u64 acc[4][4];
    #pragma unroll
    for (int u = 0; u < 4; u++)
        #pragma unroll
        for (int w = 0; w < 4; w++) acc[u][w] = 0ull;
    for (int kb = 0; kb < 512; kb += 32) {
        __syncthreads();
        #pragma unroll
        for (int q = 0; q < 4; q++) {
            int idx = t + 256 * q;
            int r = idx >> 3, c4 = (idx & 7) << 2;
            float4 av = *(const float4*)(A + (size_t)(i0 + r) * 512 + kb + c4);
            As[c4][r] = av.x; As[c4+1][r] = av.y; As[c4+2][r] = av.z; As[c4+3][r] = av.w;
        }
        #pragma unroll
        for (int q = 0; q < 2; q++) {
            int idx = t + 256 * q;
            int r2 = idx >> 4, d4 = (idx & 15) << 2;
            *(float4*)&Bs[r2][d4] = *(const float4*)(B + (size_t)(kb + r2) * 512 + j0 + d4);
        }
        __syncthreads();
        #pragma unroll
        for (int k = 0; k < 32; k++) {
            ulonglong2 a0 = *(const ulonglong2*)&As[k][ty * 8];
            ulonglong2 a1 = *(const ulonglong2*)&As[k][ty * 8 + 4];
            float4 bf = *(const float4*)&Bs[k][tx * 4];
            u64 s0 = splat2(bf.x), s1 = splat2(bf.y), s2 = splat2(bf.z), s3 = splat2(bf.w);
            u64 ar[4] = {a0.x, a0.y, a1.x, a1.y};
            #pragma unroll
            for (int u = 0; u < 4; u++) {
                acc[u][0] = ffma2(ar[u], s0, acc[u][0]);
                acc[u][1] = ffma2(ar[u], s1, acc[u][1]);
                acc[u][2] = ffma2(ar[u], s2, acc[u][2]);
                acc[u][3] = ffma2(ar[u], s3, acc[u][3]);
            }
        }
    }
    float ss = 0.f;
    #pragma unroll
    for (int u = 0; u < 4; u++) {
        int gia = i0 + ty * 8 + 2 * u;
        int gj = j0 + tx * 4;
        float2 f[4];
        #pragma unroll
        for (int w = 0; w < 4; w++) f[w] = unpk(acc[u][w]);
        float lo[4], hi[4];
        #pragma unroll
        for (int w = 0; w < 4; w++) {
            float va = f[w].x, vb = f[w].y;
            if (mode == 0) {
                va = (gia == gj + w ? 1.5f : 0.0f) - 0.5f * va;
                vb = (gia + 1 == gj + w ? 1.5f : 0.0f) - 0.5f * vb;
            } else if (mode == 2) {
                va *= scale; vb *= scale;
                ss += va * va + vb * vb;
            }
            lo[w] = va; hi[w] = vb;
        }
        *(float4*)&C[(size_t)gia * 512 + gj] = make_float4(lo[0], lo[1], lo[2], lo[3]);
        *(float4*)&C[(size_t)(gia + 1) * 512 + gj] = make_float4(hi[0], hi[1], hi[2], hi[3]);
    }
    if (mode == 2) {
        rsm[t] = ss; __syncthreads();
        for (int o = 128; o > 0; o >>= 1) { if (t < o) rsm[t] += rsm[t + o]; __syncthreads(); }
        if (t == 0) g_red2[ws][g][blockIdx.y * 8 + blockIdx.x] = rsm[0];
    }
}

// ---------------- M0 = sigma I - A, plus Frobenius^2 partials into slot 0 ----------------
__global__ __launch_bounds__(256) void k_shift() {
    int g = blockIdx.y;
    int base = blockIdx.x * 8192;
    float sigma = 1.15f * g_scal[g];
    float ss = 0.f;
    for (int q = 0; q < 32; q++) {
        int idx = base + threadIdx.x + 256 * q;
        int i = idx >> 9, j = idx & 511;
        float v = (i == j ? sigma : 0.0f) - g_A[g][i][j];
        g_M[0][g][i][j] = v;
        ss += v * v;
    }
    __shared__ float rsm[256];
    int t = threadIdx.x;
    rsm[t] = ss; __syncthreads();
    for (int o = 128; o > 0; o >>= 1) { if (t < o) rsm[t] += rsm[t + o]; __syncthreads(); }
    if (t == 0) g_red2[0][g][blockIdx.x] = rsm[0];
}

// ---------------- eigenvector extraction ----------------
__global__ void k_colnorm() {
    int g = blockIdx.x, j = threadIdx.x;
    const float* M = &g_M[0][g][0][0];
    float s = 0.f;
    for (int i = 0; i < LL; i++) { float m = M[(size_t)i * LL + j]; s += m * m; }
    __shared__ float sv[512]; __shared__ int si[512];
    sv[j] = s; si[j] = j; __syncthreads();
    for (int o = 256; o > 0; o >>= 1) {
        if (j < o) { if (sv[j + o] > sv[j]) { sv[j] = sv[j + o]; si[j] = si[j + o]; } }
        __syncthreads();
    }
    int jm = si[0];
    float inv = rsqrtf(sv[0]);
    g_v[g][j] = M[(size_t)j * LL + jm] * inv;
}

__global__ void k_rayleigh() {
    int g = blockIdx.x, i = threadIdx.x;
    __shared__ float vs[512];
    vs[i] = g_v[g][i]; __syncthreads();
    float u = 0.f;
    const float* Ac = &g_A[g][0][0];
    for (int k = 0; k < 512; k++) u = fmaf(Ac[(size_t)k * 512 + i], vs[k], u);
    __shared__ float r1[512], r2[512];
    r1[i] = u * vs[i]; r2[i] = vs[i] * vs[i]; __syncthreads();
    for (int o = 256; o > 0; o >>= 1) {
        if (i < o) { r1[i] += r1[i + o]; r2[i] += r2[i + o]; }
        __syncthreads();
    }
    if (i == 0) g_scal[8 + g] = r1[0] / r2[0];
}

// ---------------- P = Z/sqrt(c) - lam^{-1/2} v v^T ----------------
__global__ __launch_bounds__(256) void k_subspace(int zid) {
    int g = blockIdx.y;
    int idx = blockIdx.x * 256 + threadIdx.x;
    int i = idx >> 9, j = idx & 511;
    const float* Z = bufptr(zid) + (size_t)g * LL * LL;
    float c = 1.05f * g_scal[g];
    float lam = g_scal[8 + g];
    g_P[g][i][j] = Z[(size_t)i * 512 + j] * rsqrtf(c) - rsqrtf(lam) * g_v[g][i] * g_v[g][j];
}

// ---------------- beta = bias - w * (P mu)  (P symmetric -> coalesced read) ----------------
__global__ void k_beta(const float* __restrict__ w, const float* __restrict__ b) {
    int g = blockIdx.x, i = threadIdx.x;
    __shared__ float mus[512];
    mus[i] = g_mu[g * LL + i]; __syncthreads();
    float s = 0.f;
    const float* Pc = &g_P[g][0][0];
    for (int k = 0; k < 512; k++) s = fmaf(Pc[(size_t)k * 512 + i], mus[k], s);
    int c = g * LL + i;
    g_beta[c] = b[c] - w[c] * s;
}

// ---------------- apply: out = w * (P X) + beta, FFMA2 ----------------
__global__ __launch_bounds__(256) void k_apply(const float* __restrict__ x,
                                               const float* __restrict__ w,
                                               float* __restrict__ out) {
    int g = blockIdx.z;
    int i0 = blockIdx.y * 128;
    int j0 = blockIdx.x * 128;
    __shared__ float As[32][132];
    __shared__ float Bs[32][132];
    int t = threadIdx.x, tx = t & 15, ty = t >> 4;
    const float* P = &g_P[g][0][0];
    u64 acc[4][8];
    #pragma unroll
    for (int u = 0; u < 4; u++)
        #pragma unroll
        for (int wv = 0; wv < 8; wv++) acc[u][wv] = 0ull;
    for (int kb = 0; kb < 512; kb += 32) {
        __syncthreads();
        #pragma unroll
        for (int q = 0; q < 4; q++) {
            int idx = t + 256 * q;
            int r = idx >> 3, c4 = (idx & 7) << 2;
            float4 av = *(const float4*)(P + (size_t)(i0 + r) * 512 + kb + c4);
            As[c4][r] = av.x; As[c4+1][r] = av.y; As[c4+2][r] = av.z; As[c4+3][r] = av.w;
            int r2 = idx >> 5, d4 = (idx & 31) << 2;
            *(float4*)(&Bs[r2][d4]) =
                *(const float4*)(x + (size_t)(g * LL + kb + r2) * NT + j0 + d4);
        }
        __syncthreads();
        #pragma unroll
        for (int k = 0; k < 32; k++) {
            ulonglong2 a0 = *(const ulonglong2*)&As[k][ty * 8];
            ulonglong2 a1 = *(const ulonglong2*)&As[k][ty * 8 + 4];
            float4 b0 = *(const float4*)&Bs[k][tx * 8];
            float4 b1 = *(const float4*)&Bs[k][tx * 8 + 4];
            u64 s0 = splat2(b0.x), s1 = splat2(b0.y), s2 = splat2(b0.z), s3 = splat2(b0.w);
            u64 s4 = splat2(b1.x), s5 = splat2(b1.y), s6 = splat2(b1.z), s7 = splat2(b1.w);
            u64 ar[4] = {a0.x, a0.y, a1.x, a1.y};
            #pragma unroll
            for (int u = 0; u < 4; u++) {
                acc[u][0] = ffma2(ar[u], s0, acc[u][0]);
                acc[u][1] = ffma2(ar[u], s1, acc[u][1]);
                acc[u][2] = ffma2(ar[u], s2, acc[u][2]);
                acc[u][3] = ffma2(ar[u], s3, acc[u][3]);
                acc[u][4] = ffma2(ar[u], s4, acc[u][4]);
                acc[u][5] = ffma2(ar[u], s5, acc[u][5]);
                acc[u][6] = ffma2(ar[u], s6, acc[u][6]);
                acc[u][7] = ffma2(ar[u], s7, acc[u][7]);
            }
        }
    }
    #pragma unroll
    for (int u = 0; u < 4; u++) {
        int cha = g * LL + i0 + ty * 8 + 2 * u;
        float wa = w[cha], ba = g_beta[cha];
        float wb = w[cha + 1], bb = g_beta[cha + 1];
        float2 f[8];
        #pragma unroll
        for (int wv = 0; wv < 8; wv++) f[wv] = unpk(acc[u][wv]);
        float* orow_a = out + (size_t)cha * NT + j0 + tx * 8;
        float* orow_b = out + (size_t)(cha + 1) * NT + j0 + tx * 8;
        float4 va0, va1, vb0, vb1;
        va0.x = fmaf(wa, f[0].x, ba); va0.y = fmaf(wa, f[1].x, ba);
        va0.z = fmaf(wa, f[2].x, ba); va0.w = fmaf(wa, f[3].x, ba);
        va1.x = fmaf(wa, f[4].x, ba); va1.y = fmaf(wa, f[5].x, ba);
        va1.z = fmaf(wa, f[6].x, ba); va1.w = fmaf(wa, f[7].x, ba);
        vb0.x = fmaf(wb, f[0].y, bb); vb0.y = fmaf(wb, f[1].y, bb);
        vb0.z = fmaf(wb, f[2].y, bb); vb0.w = fmaf(wb, f[3].y, bb);
        vb1.x = fmaf(wb, f[4].y, bb); vb1.y = fmaf(wb, f[5].y, bb);
        vb1.z = fmaf(wb, f[6].y, bb); vb1.w = fmaf(wb, f[7].y, bb);
        *(float4*)(orow_a) = va0; *(float4*)(orow_a + 4) = va1;
        *(float4*)(orow_b) = vb0; *(float4*)(orow_b + 4) = vb1;
    }
}

// ---------------- launch ----------------
extern "C" void kernel_launch(void* const* d_in, const int* in_sizes, int n_in,
                              void* d_out, int out_size) {
    const float* x = (const float*)d_in[0];
    const float* w = (const float*)d_in[1];
    const float* b = (const float*)d_in[2];
    float* out = (float*)d_out;

    k_mean<<<CC, 256>>>(x);
    k_cov<<<dim3(10, GG, KS), 256>>>(x);
    k_cov_reduce<<<dim3(1024, GG), 256>>>();

    k_pi_init<<<8, 256>>>();
    for (int m = 0; m < 7; m++)
        k_matvec<<<dim3(16, GG), 256>>>(m & 1);
    k_rq<<<GG, 512>>>();

    // Newton-Schulz (4 effective iterations, 9 GEMMs)
    // ids: 0=Y[0] 1=Y[1] 2=Z[0] 3=Z[1] 4=T
    k_ns_init<<<dim3(1024, GG), 256>>>();                      // Y0->0, T0(=Z1)->2
    dim3 gg(8, 4, GG);
    k_gemm512<<<gg, 256>>>(0, 2, 1, 1, 0, 0);                  // Y1 = Y0 T0 -> 1
    k_gemm512<<<gg, 256>>>(2, 1, 4, 0, 0, 0);                  // T = 1.5I-0.5 Z1 Y1
    k_gemm512<<<gg, 256>>>(1, 4, 0, 1, 0, 0);                  // Y2 -> 0
    k_gemm512<<<gg, 256>>>(4, 2, 3, 1, 0, 0);                  // Z2 -> 3
    k_gemm512<<<gg, 256>>>(3, 0, 4, 0, 0, 0);                  // T
    k_gemm512<<<gg, 256>>>(0, 4, 1, 1, 0, 0);                  // Y3 -> 1
    k_gemm512<<<gg, 256>>>(4, 3, 2, 1, 0, 0);                  // Z3 -> 2
    k_gemm512<<<gg, 256>>>(2, 1, 4, 0, 0, 0);                  // T
    k_gemm512<<<gg, 256>>>(4, 2, 3, 1, 0, 0);                  // Z4 -> 3 (final)

    // smallest eigenpair via repeated squaring of (sigma I - A)
    k_shift<<<dim3(32, GG), 256>>>();
    for (int k = 0; k < SQ_ITERS; k++) {
        int inb = 5 + (k & 1), outb = 5 + 1 - (k & 1);
        k_gemm512<<<gg, 256>>>(inb, inb, outb, 2, k & 1, 1 - (k & 1));
    }

    k_colnorm<<<GG, 512>>>();
    k_rayleigh<<<GG, 512>>>();
    k_subspace<<<dim3(1024, GG), 256>>>(3);
    k_beta<<<GG, 512>>>(w, b);
    k_apply<<<dim3(128, 4, GG), 256>>>(x, w, out);
}